// round 13
// baseline (speedup 1.0000x reference)
#include <cuda_runtime.h>
#include <cuda_fp16.h>
#include <cstdint>
#include <math.h>

#define NNODES 2048
#define NEDGES 65536
#define NB     8
#define FMAX   1024
#define NROWS  (NB * NNODES)   // 16384
#define BN_EPS 1e-5f

// ==================== device scratch ====================
__device__ int   g_is64;
__device__ int   g_deg[NNODES];
__device__ float g_dinv[NNODES];
__device__ int   g_off[NNODES + 1];
__device__ int   g_cursor[NNODES];
__device__ int   g_csr_src[NEDGES];
__device__ float g_csr_norm[NEDGES];
__device__ float g_alpha[NB * FMAX];
__device__ float g_beta[NB * FMAX];
__device__ float g_sum[NB * FMAX];
__device__ float g_sum2[NB * FMAX];
__device__ int   g_ctr = 0;     // last-CTA election counter (self-resetting)
__device__ __align__(16) __half g_Phi[(size_t)NROWS * FMAX];
__device__ __align__(16) __half g_Plo[(size_t)NROWS * FMAX];
#define WTOTAL 2768896
__device__ __align__(16) __half g_Whi[WTOTAL];
__device__ __align__(16) __half g_Wlo[WTOTAL];
__device__ __align__(16) float  g_T[(size_t)NROWS * FMAX];    // fp32 hidden (layer-0 out, layer-4 out)
__device__ __align__(16) __half g_T16[(size_t)NROWS * FMAX];  // fp16 hidden (layer-1/2/3 outputs)

// ==================== graph preprocessing ====================
__device__ __forceinline__ int edge_val(const void* edges, int idx) {
    if (g_is64) return (int)((const long long*)edges)[idx];
    return ((const int*)edges)[idx];
}
__global__ void detect_zero_kernel(const void* edges) {
    int i = blockIdx.x * blockDim.x + threadIdx.x;
    if (i < NNODES) g_deg[i] = 0;
    if (i == 0) {
        const long long* p = (const long long*)edges;
        int is64 = 1;
        for (int k = 0; k < 16; k++) {
            long long v = p[k];
            if (v < 0 || v >= NNODES) is64 = 0;
        }
        g_is64 = is64;
    }
}
__global__ void count_deg_kernel(const void* edges) {
    int e = blockIdx.x * blockDim.x + threadIdx.x;
    if (e < NEDGES) atomicAdd(&g_deg[edge_val(edges, NEDGES + e)], 1);
}
__global__ void scan_kernel() {
    __shared__ int part[1024];
    int t = threadIdx.x;
    int c0 = g_deg[2 * t];
    int c1 = g_deg[2 * t + 1];
    part[t] = c0 + c1;
    __syncthreads();
    for (int off = 1; off < 1024; off <<= 1) {
        int v = (t >= off) ? part[t - off] : 0;
        __syncthreads();
        part[t] += v;
        __syncthreads();
    }
    int base = (t > 0) ? part[t - 1] : 0;
    g_off[2 * t] = base;        g_off[2 * t + 1] = base + c0;
    g_cursor[2 * t] = base;     g_cursor[2 * t + 1] = base + c0;
    g_dinv[2 * t]     = rsqrtf((float)(c0 + 1));
    g_dinv[2 * t + 1] = rsqrtf((float)(c1 + 1));
    if (t == 1023) g_off[2048] = part[1023];
}
__global__ void fill_kernel(const void* edges) {
    int e = blockIdx.x * blockDim.x + threadIdx.x;
    if (e < NEDGES) {
        int s = edge_val(edges, e);
        int d = edge_val(edges, NEDGES + e);
        int p = atomicAdd(&g_cursor[d], 1);
        g_csr_src[p]  = s;
        g_csr_norm[p] = g_dinv[s] * g_dinv[d];
    }
}

// ==================== fp16 hi/lo split helpers ====================
__device__ __forceinline__ void split_h(float v, __half& hi, __half& lo) {
    hi = __float2half_rn(v);
    lo = __float2half_rn(v - __half2float(hi));
}
__device__ __forceinline__ void split4(const float4 v, uint2& hi, uint2& lo) {
    __half h0, l0, h1, l1, h2, l2, h3, l3;
    split_h(v.x, h0, l0); split_h(v.y, h1, l1);
    split_h(v.z, h2, l2); split_h(v.w, h3, l3);
    __half2 ha = __halves2half2(h0, h1), hb = __halves2half2(h2, h3);
    __half2 la = __halves2half2(l0, l1), lb = __halves2half2(l2, l3);
    hi = make_uint2(*(uint32_t*)&ha, *(uint32_t*)&hb);
    lo = make_uint2(*(uint32_t*)&la, *(uint32_t*)&lb);
}

// ==================== weight conversion ====================
__constant__ int c_woff4[6] = {0, 4096, 36864, 167936, 430080, 692224}; // float4 units
__global__ void convert_all_w_kernel(const float* __restrict__ w1, const float* __restrict__ w2,
                                     const float* __restrict__ w3, const float* __restrict__ w4,
                                     const float* __restrict__ w5) {
    int i = blockIdx.x * blockDim.x + threadIdx.x;
    if (i >= 692224) return;
    const float* src;
    int local;
    if (i < c_woff4[1])      { src = w1; local = i; }
    else if (i < c_woff4[2]) { src = w2; local = i - c_woff4[1]; }
    else if (i < c_woff4[3]) { src = w3; local = i - c_woff4[2]; }
    else if (i < c_woff4[4]) { src = w4; local = i - c_woff4[3]; }
    else                     { src = w5; local = i - c_woff4[4]; }
    float4 v = ((const float4*)src)[local];
    uint2 hi, lo;
    split4(v, hi, lo);
    ((uint2*)g_Whi)[i] = hi;
    ((uint2*)g_Wlo)[i] = lo;
}

// ==================== aggregation fp32 input (layers 0-1), unroll-2 ====================
template <int F, bool BN>
__global__ void agg_kernel(const float* __restrict__ Hsrc,
                           __half* __restrict__ Phi, __half* __restrict__ Plo) {
    constexpr int F4 = F / 4;
    int b = blockIdx.y;
    if (blockIdx.x == 0) {
        int ft = threadIdx.y * blockDim.x + threadIdx.x;
        for (int i = ft; i < FMAX; i += 256) {
            g_sum[b * FMAX + i]  = 0.f;
            g_sum2[b * FMAX + i] = 0.f;
        }
    }
    int node = blockIdx.x * blockDim.y + threadIdx.y;
    int f4   = threadIdx.x;
    const float4* Hb = reinterpret_cast<const float4*>(Hsrc) + (size_t)b * NNODES * F4;

    float wself = g_dinv[node] * g_dinv[node];
    float4 hv = Hb[(size_t)node * F4 + f4];
    float4 acc = make_float4(wself * hv.x, wself * hv.y, wself * hv.z, wself * hv.w);
    float4 acc2 = make_float4(0.f, 0.f, 0.f, 0.f);
    float wsum = wself, wsum2 = 0.f;

    int beg = g_off[node], end = g_off[node + 1];
    int e = beg;
    for (; e + 2 <= end; e += 2) {
        int   s0 = g_csr_src[e],  s1 = g_csr_src[e + 1];
        float w0 = g_csr_norm[e], w1 = g_csr_norm[e + 1];
        float4 h0 = Hb[(size_t)s0 * F4 + f4];
        float4 h1 = Hb[(size_t)s1 * F4 + f4];
        acc.x  += w0 * h0.x; acc.y  += w0 * h0.y; acc.z  += w0 * h0.z; acc.w  += w0 * h0.w;
        acc2.x += w1 * h1.x; acc2.y += w1 * h1.y; acc2.z += w1 * h1.z; acc2.w += w1 * h1.w;
        wsum += w0; wsum2 += w1;
    }
    if (e < end) {
        int   s = g_csr_src[e];
        float w = g_csr_norm[e];
        float4 h = Hb[(size_t)s * F4 + f4];
        acc.x += w * h.x; acc.y += w * h.y; acc.z += w * h.z; acc.w += w * h.w;
        wsum += w;
    }
    acc.x += acc2.x; acc.y += acc2.y; acc.z += acc2.z; acc.w += acc2.w;
    wsum += wsum2;

    if (BN) {
        float4 al = ((const float4*)g_alpha)[b * (FMAX / 4) + f4];
        float4 bt = ((const float4*)g_beta)[b * (FMAX / 4) + f4];
        acc.x = acc.x * al.x + bt.x * wsum;
        acc.y = acc.y * al.y + bt.y * wsum;
        acc.z = acc.z * al.z + bt.z * wsum;
        acc.w = acc.w * al.w + bt.w * wsum;
    }
    uint2 hi, lo;
    split4(acc, hi, lo);
    size_t idx = ((size_t)b * NNODES + node) * F4 + f4;
    ((uint2*)Phi)[idx] = hi;
    ((uint2*)Plo)[idx] = lo;
}

// ==================== aggregation fp16 input (F=512/1024), 8 feats/thread, 16B loads, unroll-4 ====================
__device__ __forceinline__ void h8_to_f(const uint4 u, float* f) {
    float2 a = __half22float2(*(__half2*)&u.x);
    float2 b = __half22float2(*(__half2*)&u.y);
    float2 c = __half22float2(*(__half2*)&u.z);
    float2 d = __half22float2(*(__half2*)&u.w);
    f[0] = a.x; f[1] = a.y; f[2] = b.x; f[3] = b.y;
    f[4] = c.x; f[5] = c.y; f[6] = d.x; f[7] = d.y;
}
template <int F>
__global__ __launch_bounds__(256) void agg_f16_kernel(
    const __half* __restrict__ Hsrc, __half* __restrict__ Phi, __half* __restrict__ Plo) {
    constexpr int F8 = F / 8;
    int b = blockIdx.y;
    if (blockIdx.x == 0) {
        int ft = threadIdx.y * blockDim.x + threadIdx.x;
        for (int i = ft; i < FMAX; i += 256) {
            g_sum[b * FMAX + i]  = 0.f;
            g_sum2[b * FMAX + i] = 0.f;
        }
    }
    int node = blockIdx.x * blockDim.y + threadIdx.y;
    int f8   = threadIdx.x;
    const uint4* Hb = reinterpret_cast<const uint4*>(Hsrc) + (size_t)b * NNODES * F8;

    float wself = g_dinv[node] * g_dinv[node];
    float hv[8];
    h8_to_f(Hb[(size_t)node * F8 + f8], hv);
    float acc[8], acc2[8];
#pragma unroll
    for (int j = 0; j < 8; j++) { acc[j] = wself * hv[j]; acc2[j] = 0.f; }
    float wsum = wself, wsum2 = 0.f;

    int beg = g_off[node], end = g_off[node + 1];
    int e = beg;
    for (; e + 4 <= end; e += 4) {
        int   s0 = g_csr_src[e],     s1 = g_csr_src[e + 1];
        int   s2 = g_csr_src[e + 2], s3 = g_csr_src[e + 3];
        float w0 = g_csr_norm[e],     w1 = g_csr_norm[e + 1];
        float w2 = g_csr_norm[e + 2], w3 = g_csr_norm[e + 3];
        uint4 u0 = Hb[(size_t)s0 * F8 + f8];
        uint4 u1 = Hb[(size_t)s1 * F8 + f8];
        uint4 u2 = Hb[(size_t)s2 * F8 + f8];
        uint4 u3 = Hb[(size_t)s3 * F8 + f8];
        float h0[8], h1[8], h2[8], h3[8];
        h8_to_f(u0, h0); h8_to_f(u1, h1); h8_to_f(u2, h2); h8_to_f(u3, h3);
#pragma unroll
        for (int j = 0; j < 8; j++) {
            acc[j]  += w0 * h0[j] + w2 * h2[j];
            acc2[j] += w1 * h1[j] + w3 * h3[j];
        }
        wsum += w0 + w2; wsum2 += w1 + w3;
    }
    for (; e < end; e++) {
        int   s = g_csr_src[e];
        float w = g_csr_norm[e];
        float h[8];
        h8_to_f(Hb[(size_t)s * F8 + f8], h);
#pragma unroll
        for (int j = 0; j < 8; j++) acc[j] += w * h[j];
        wsum += w;
    }
#pragma unroll
    for (int j = 0; j < 8; j++) acc[j] += acc2[j];
    wsum += wsum2;

    // BN affine (8 channels)
    float4 al0 = ((const float4*)g_alpha)[b * (FMAX / 4) + f8 * 2];
    float4 al1 = ((const float4*)g_alpha)[b * (FMAX / 4) + f8 * 2 + 1];
    float4 bt0 = ((const float4*)g_beta)[b * (FMAX / 4) + f8 * 2];
    float4 bt1 = ((const float4*)g_beta)[b * (FMAX / 4) + f8 * 2 + 1];
    float4 r0 = make_float4(acc[0] * al0.x + bt0.x * wsum, acc[1] * al0.y + bt0.y * wsum,
                            acc[2] * al0.z + bt0.z * wsum, acc[3] * al0.w + bt0.w * wsum);
    float4 r1 = make_float4(acc[4] * al1.x + bt1.x * wsum, acc[5] * al1.y + bt1.y * wsum,
                            acc[6] * al1.z + bt1.z * wsum, acc[7] * al1.w + bt1.w * wsum);
    uint2 hiA, loA, hiB, loB;
    split4(r0, hiA, loA);
    split4(r1, hiB, loB);
    size_t idx = ((size_t)b * NNODES + node) * F8 + f8;
    ((uint4*)Phi)[idx] = make_uint4(hiA.x, hiA.y, hiB.x, hiB.y);
    ((uint4*)Plo)[idx] = make_uint4(loA.x, loA.y, loB.x, loB.y);
}

// ==================== mma.sync GEMM: 128 thr, warp tile 64x64, 2-stage, 2 CTA/SM ====================
// Fused BN-stat finalize via last-CTA election (replaces stats_final_kernel).
#define TK        32
#define SM_STRIDE 80
#define MAT_BYTES (128 * SM_STRIDE)       // 10240
#define STAGE_BYTES (4 * MAT_BYTES)       // 40960
#define GEMM_SMEM (2 * STAGE_BYTES)       // 81920

__device__ __forceinline__ void cp_async16(uint32_t saddr, const void* gptr) {
    asm volatile("cp.async.cg.shared.global [%0], [%1], 16;" :: "r"(saddr), "l"(gptr));
}
__device__ __forceinline__ void ldm_x4(uint32_t* r, uint32_t addr) {
    asm volatile("ldmatrix.sync.aligned.m8n8.x4.shared.b16 {%0,%1,%2,%3}, [%4];"
        : "=r"(r[0]), "=r"(r[1]), "=r"(r[2]), "=r"(r[3]) : "r"(addr));
}
__device__ __forceinline__ void mma16816(float* c, const uint32_t* a, const uint32_t* b) {
    asm volatile("mma.sync.aligned.m16n8k16.row.col.f32.f16.f16.f32 "
        "{%0,%1,%2,%3}, {%4,%5,%6,%7}, {%8,%9}, {%0,%1,%2,%3};"
        : "+f"(c[0]), "+f"(c[1]), "+f"(c[2]), "+f"(c[3])
        : "r"(a[0]), "r"(a[1]), "r"(a[2]), "r"(a[3]), "r"(b[0]), "r"(b[1]));
}
__device__ __forceinline__ uint32_t smem_u32(const void* p) {
    uint32_t a;
    asm("{ .reg .u64 t; cvta.to.shared.u64 t, %1; cvt.u32.u64 %0, t; }" : "=r"(a) : "l"(p));
    return a;
}

template <bool HALF_OUT>
__global__ __launch_bounds__(128, 2) void mma_gemm_kernel(
    const __half* __restrict__ Ahi, const __half* __restrict__ Alo,
    const __half* __restrict__ Bhi, const __half* __restrict__ Blo,
    const float* __restrict__ bias, void* __restrict__ Cout, int K, int O,
    const float* __restrict__ gam, const float* __restrict__ bet) {
    extern __shared__ __align__(16) char smem[];
    uint32_t sb = smem_u32(smem);
    int tid  = threadIdx.x;
    int lane = tid & 31, wid = tid >> 5;
    int wm = wid >> 1, wn = wid & 1;
    int brow = blockIdx.y * 128;
    int bcol = blockIdx.x * 128;

    float acc[4][32];
#pragma unroll
    for (int i = 0; i < 4; i++)
#pragma unroll
        for (int j = 0; j < 32; j++) acc[i][j] = 0.f;

    const int NC = K / TK;
    auto load_stage = [&](int i) {
        int kc = i * TK;
        uint32_t st = sb + (uint32_t)(i & 1) * STAGE_BYTES;
#pragma unroll
        for (int c = 0; c < 4; c++) {
            int idx = tid + 128 * c;
            int row = idx >> 2, q = idx & 3;
            uint32_t soff = (uint32_t)(row * SM_STRIDE + q * 16);
            size_t gA = (size_t)(brow + row) * K + kc + q * 8;
            size_t gB = (size_t)(bcol + row) * K + kc + q * 8;
            cp_async16(st + soff,                 Ahi + gA);
            cp_async16(st + MAT_BYTES + soff,     Alo + gA);
            cp_async16(st + 2 * MAT_BYTES + soff, Bhi + gB);
            cp_async16(st + 3 * MAT_BYTES + soff, Blo + gB);
        }
        asm volatile("cp.async.commit_group;");
    };

    int grp = lane >> 3, l7 = lane & 7;
    uint32_t aOff = (uint32_t)((wm * 64 + (grp & 1) * 8 + l7) * SM_STRIDE + (grp >> 1) * 16);
    uint32_t bOff = (uint32_t)((wn * 64 + (grp >> 1) * 8 + l7) * SM_STRIDE + (grp & 1) * 16);

    load_stage(0);
    for (int i = 0; i < NC; i++) {
        if (i + 1 < NC) {
            load_stage(i + 1);
            asm volatile("cp.async.wait_group 1;");
        } else {
            asm volatile("cp.async.wait_group 0;");
        }
        __syncthreads();
        uint32_t st = sb + (uint32_t)(i & 1) * STAGE_BYTES;
#pragma unroll
        for (int ks = 0; ks < 2; ks++) {
            uint32_t ah[4][4], al[4][4], bh[4][4], bl[4][4];
#pragma unroll
            for (int mt = 0; mt < 4; mt++) {
                uint32_t a = st + aOff + (uint32_t)(mt * 16 * SM_STRIDE + ks * 32);
                ldm_x4(ah[mt], a);
                ldm_x4(al[mt], a + MAT_BYTES);
            }
#pragma unroll
            for (int ng = 0; ng < 4; ng++) {
                uint32_t b = st + 2 * MAT_BYTES + bOff + (uint32_t)(ng * 16 * SM_STRIDE + ks * 32);
                ldm_x4(bh[ng], b);
                ldm_x4(bl[ng], b + MAT_BYTES);
            }
#pragma unroll
            for (int mt = 0; mt < 4; mt++)
#pragma unroll
                for (int n8 = 0; n8 < 8; n8++) {
                    float* cc = &acc[mt][n8 * 4];
                    const uint32_t* bhf = &bh[n8 >> 1][(n8 & 1) * 2];
                    const uint32_t* blf = &bl[n8 >> 1][(n8 & 1) * 2];
                    mma16816(cc, ah[mt], bhf);
                    mma16816(cc, al[mt], bhf);
                    mma16816(cc, ah[mt], blf);
                }
        }
        __syncthreads();
    }

    // epilogue: bias + leaky, store (fp32 or fp16), fused BN partial stats
    int b = brow >> 11;
    int r0base = brow + wm * 64 + (lane >> 2);
    int cbase  = bcol + wn * 64 + (lane & 3) * 2;
    float s0[8], q0[8], s1[8], q1[8];
#pragma unroll
    for (int n8 = 0; n8 < 8; n8++) { s0[n8] = q0[n8] = s1[n8] = q1[n8] = 0.f; }
#pragma unroll
    for (int mt = 0; mt < 4; mt++) {
#pragma unroll
        for (int n8 = 0; n8 < 8; n8++) {
            int c  = cbase + n8 * 8;
            float2 bz = *(const float2*)(bias + c);
            float* a4 = &acc[mt][n8 * 4];
            float v0 = a4[0] + bz.x, v1 = a4[1] + bz.y;
            float v2 = a4[2] + bz.x, v3 = a4[3] + bz.y;
            v0 = (v0 > 0.f) ? v0 : 0.01f * v0;
            v1 = (v1 > 0.f) ? v1 : 0.01f * v1;
            v2 = (v2 > 0.f) ? v2 : 0.01f * v2;
            v3 = (v3 > 0.f) ? v3 : 0.01f * v3;
            int r0 = r0base + mt * 16;
            if (HALF_OUT) {
                __half* C16 = (__half*)Cout;
                *(__half2*)(C16 + (size_t)r0 * O + c)       = __floats2half2_rn(v0, v1);
                *(__half2*)(C16 + (size_t)(r0 + 8) * O + c) = __floats2half2_rn(v2, v3);
            } else {
                float* C = (float*)Cout;
                *(float2*)(C + (size_t)r0 * O + c)       = make_float2(v0, v1);
                *(float2*)(C + (size_t)(r0 + 8) * O + c) = make_float2(v2, v3);
            }
            s0[n8] += v0 + v2;  q0[n8] += v0 * v0 + v2 * v2;
            s1[n8] += v1 + v3;  q1[n8] += v1 * v1 + v3 * v3;
        }
    }
#pragma unroll
    for (int n8 = 0; n8 < 8; n8++) {
        float a = s0[n8], bq = q0[n8], cs = s1[n8], dq = q1[n8];
#pragma unroll
        for (int m = 4; m <= 16; m <<= 1) {
            a  += __shfl_xor_sync(0xffffffffu, a,  m);
            bq += __shfl_xor_sync(0xffffffffu, bq, m);
            cs += __shfl_xor_sync(0xffffffffu, cs, m);
            dq += __shfl_xor_sync(0xffffffffu, dq, m);
        }
        if (lane < 4) {
            int c = cbase + n8 * 8;
            atomicAdd(&g_sum[b * FMAX + c],      a);
            atomicAdd(&g_sum2[b * FMAX + c],     bq);
            atomicAdd(&g_sum[b * FMAX + c + 1],  cs);
            atomicAdd(&g_sum2[b * FMAX + c + 1], dq);
        }
    }

    // ---- last-CTA election: finalize alpha/beta (replaces stats_final launch) ----
    __shared__ int is_last;
    __threadfence();
    if (tid == 0) {
        int c = atomicAdd(&g_ctr, 1);
        is_last = (c == (int)(gridDim.x * gridDim.y) - 1) ? 1 : 0;
    }
    __syncthreads();
    if (is_last) {
        if (tid == 0) g_ctr = 0;   // reset for next launch (deterministic across replays)
        volatile float* vs  = g_sum;
        volatile float* vs2 = g_sum2;
        int total = NB * O;
        for (int i = tid; i < total; i += 128) {
            int bb = i / O, o = i % O;
            float mu  = vs[bb * FMAX + o] * (1.0f / NNODES);
            float var = vs2[bb * FMAX + o] * (1.0f / NNODES) - mu * mu;
            if (var < 0.f) var = 0.f;
            float aa = gam[o] * rsqrtf(var + BN_EPS);
            g_alpha[bb * FMAX + o] = aa;
            g_beta[bb * FMAX + o]  = bet[o] - mu * aa;
        }
        __threadfence();
    }
}

// ==================== final: BN apply + LayerNorm ====================
__global__ void final_kernel(const float* __restrict__ T, const float* __restrict__ ln_g,
                             const float* __restrict__ ln_b, float* __restrict__ out) {
    const int O = 1024;
    int b = blockIdx.y, n = blockIdx.x, t = threadIdx.x;
    size_t rowbase = ((size_t)b * NNODES + n) * O;
    float4 tv = ((const float4*)(T + rowbase))[t];
    float4 av = ((const float4*)g_alpha)[b * (FMAX / 4) + t];
    float4 cv = ((const float4*)g_beta)[b * (FMAX / 4) + t];
    float4 v;
    v.x = tv.x * av.x + cv.x; v.y = tv.y * av.y + cv.y;
    v.z = tv.z * av.z + cv.z; v.w = tv.w * av.w + cv.w;

    float s  = v.x + v.y + v.z + v.w;
    float s2 = v.x * v.x + v.y * v.y + v.z * v.z + v.w * v.w;
#pragma unroll
    for (int off = 16; off > 0; off >>= 1) {
        s  += __shfl_xor_sync(0xffffffffu, s, off);
        s2 += __shfl_xor_sync(0xffffffffu, s2, off);
    }
    __shared__ float ss[8], ss2[8];
    __shared__ float mu_s, r_s;
    int warp = t >> 5, lane = t & 31;
    if (lane == 0) { ss[warp] = s; ss2[warp] = s2; }
    __syncthreads();
    if (t == 0) {
        float S = 0.f, S2 = 0.f;
        for (int i = 0; i < 8; i++) { S += ss[i]; S2 += ss2[i]; }
        float mu  = S * (1.0f / O);
        float var = S2 * (1.0f / O) - mu * mu;
        if (var < 0.f) var = 0.f;
        mu_s = mu;
        r_s  = rsqrtf(var + BN_EPS);
    }
    __syncthreads();
    float mu = mu_s, r = r_s;
    float4 g4 = ((const float4*)ln_g)[t];
    float4 b4 = ((const float4*)ln_b)[t];
    float4 o;
    o.x = (v.x - mu) * r * g4.x + b4.x;
    o.y = (v.y - mu) * r * g4.y + b4.y;
    o.z = (v.z - mu) * r * g4.z + b4.z;
    o.w = (v.w - mu) * r * g4.w + b4.w;
    ((float4*)(out + rowbase))[t] = o;
}

// ==================== host ====================
extern "C" void kernel_launch(void* const* d_in, const int* in_sizes, int n_in,
                              void* d_out, int out_size) {
    const float *x, *w[5], *bb[5], *gg[5], *be[5], *lng, *lnb;
    const void* edges;
    if (in_sizes[0] == 16384) {
        for (int i = 0; i < 5; i++) {
            w[i]  = (const float*)d_in[4 * i + 0];
            bb[i] = (const float*)d_in[4 * i + 1];
            gg[i] = (const float*)d_in[4 * i + 2];
            be[i] = (const float*)d_in[4 * i + 3];
        }
        lng = (const float*)d_in[20];
        lnb = (const float*)d_in[21];
        x   = (const float*)d_in[22];
        edges = d_in[23];
    } else {
        x     = (const float*)d_in[0];
        edges = d_in[1];
        for (int i = 0; i < 5; i++) {
            w[i]  = (const float*)d_in[2 + 4 * i + 0];
            bb[i] = (const float*)d_in[2 + 4 * i + 1];
            gg[i] = (const float*)d_in[2 + 4 * i + 2];
            be[i] = (const float*)d_in[2 + 4 * i + 3];
        }
        lng = (const float*)d_in[22];
        lnb = (const float*)d_in[23];
    }

    static int smem_set = 0;
    if (!smem_set) {
        cudaFuncSetAttribute(mma_gemm_kernel<false>, cudaFuncAttributeMaxDynamicSharedMemorySize, GEMM_SMEM);
        cudaFuncSetAttribute(mma_gemm_kernel<true>,  cudaFuncAttributeMaxDynamicSharedMemorySize, GEMM_SMEM);
        smem_set = 1;
    }

    __half *Phi, *Plo, *Whi, *Wlo, *T16;
    float* T;
    cudaGetSymbolAddress((void**)&Phi, g_Phi);
    cudaGetSymbolAddress((void**)&Plo, g_Plo);
    cudaGetSymbolAddress((void**)&Whi, g_Whi);
    cudaGetSymbolAddress((void**)&Wlo, g_Wlo);
    cudaGetSymbolAddress((void**)&T,   g_T);
    cudaGetSymbolAddress((void**)&T16, g_T16);

    convert_all_w_kernel<<<(692224 + 255) / 256, 256>>>(w[0], w[1], w[2], w[3], w[4]);
    detect_zero_kernel<<<8, 256>>>(edges);
    count_deg_kernel<<<NEDGES / 256, 256>>>(edges);
    scan_kernel<<<1, 1024>>>();
    fill_kernel<<<NEDGES / 256, 256>>>(edges);

    const int dout[5] = {256, 512, 1024, 1024, 1024};
    const int din[5]  = {64, 256, 512, 1024, 1024};
    const int woff[5] = {0, 16384, 147456, 671744, 1720320};
    for (int l = 0; l < 5; l++) {
        int K = din[l], O = dout[l];
        // aggregation: L0 reads x fp32; L1 reads T fp32 (K=256); L2-4 read T16 fp16
        if (l == 0)
            agg_kernel<64, false><<<dim3(NNODES / 16, NB), dim3(16, 16)>>>(x, Phi, Plo);
        else if (l == 1)
            agg_kernel<256, true><<<dim3(NNODES / 4, NB), dim3(64, 4)>>>(T, Phi, Plo);
        else if (l == 2)
            agg_f16_kernel<512><<<dim3(NNODES / 4, NB), dim3(64, 4)>>>(T16, Phi, Plo);
        else
            agg_f16_kernel<1024><<<dim3(NNODES / 2, NB), dim3(128, 2)>>>(T16, Phi, Plo);
        // GEMM (with fused BN-stat finalize): layers 1-3 emit fp16; 0 and 4 emit fp32
        if (l >= 1 && l <= 3)
            mma_gemm_kernel<true><<<dim3(O / 128, NROWS / 128), 128, GEMM_SMEM>>>(
                Phi, Plo, Whi + woff[l], Wlo + woff[l], bb[l], (void*)T16, K, O, gg[l], be[l]);
        else
            mma_gemm_kernel<false><<<dim3(O / 128, NROWS / 128), 128, GEMM_SMEM>>>(
                Phi, Plo, Whi + woff[l], Wlo + woff[l], bb[l], (void*)T, K, O, gg[l], be[l]);
        if (l == 4) final_kernel<<<dim3(NNODES, NB), 256>>>(T, lng, lnb, (float*)d_out);
    }
}

// round 14
// speedup vs baseline: 1.1219x; 1.1219x over previous
#include <cuda_runtime.h>
#include <cuda_fp16.h>
#include <cstdint>
#include <math.h>

#define NNODES 2048
#define NEDGES 65536
#define NB     8
#define FMAX   1024
#define NROWS  (NB * NNODES)   // 16384
#define BN_EPS 1e-5f

// ==================== device scratch ====================
__device__ int   g_is64;
__device__ int   g_deg[NNODES];
__device__ float g_dinv[NNODES];
__device__ int   g_off[NNODES + 1];
__device__ int   g_cursor[NNODES];
__device__ int   g_csr_src[NEDGES];
__device__ float g_csr_norm[NEDGES];
__device__ float g_alpha[NB * FMAX];
__device__ float g_beta[NB * FMAX];
__device__ float g_sum[NB * FMAX];
__device__ float g_sum2[NB * FMAX];
__device__ __align__(16) __half g_Phi[(size_t)NROWS * FMAX];
__device__ __align__(16) __half g_Plo[(size_t)NROWS * FMAX];
#define WTOTAL 2768896
__device__ __align__(16) __half g_Whi[WTOTAL];
__device__ __align__(16) __half g_Wlo[WTOTAL];
__device__ __align__(16) float  g_T[(size_t)NROWS * FMAX];    // fp32 hidden (layer-0 out, layer-4 out)
__device__ __align__(16) __half g_T16[(size_t)NROWS * FMAX];  // fp16 hidden (layer-1/2/3 outputs)

// ==================== fp16 hi/lo split helpers ====================
__device__ __forceinline__ void split_h(float v, __half& hi, __half& lo) {
    hi = __float2half_rn(v);
    lo = __float2half_rn(v - __half2float(hi));
}
__device__ __forceinline__ void split4(const float4 v, uint2& hi, uint2& lo) {
    __half h0, l0, h1, l1, h2, l2, h3, l3;
    split_h(v.x, h0, l0); split_h(v.y, h1, l1);
    split_h(v.z, h2, l2); split_h(v.w, h3, l3);
    __half2 ha = __halves2half2(h0, h1), hb = __halves2half2(h2, h3);
    __half2 la = __halves2half2(l0, l1), lb = __halves2half2(l2, l3);
    hi = make_uint2(*(uint32_t*)&ha, *(uint32_t*)&hb);
    lo = make_uint2(*(uint32_t*)&la, *(uint32_t*)&lb);
}

// ==================== weight conversion + deg-zero + edge-dtype detect (merged) ====================
__constant__ int c_woff4[6] = {0, 4096, 36864, 167936, 430080, 692224}; // float4 units
__global__ void convert_all_w_kernel(const float* __restrict__ w1, const float* __restrict__ w2,
                                     const float* __restrict__ w3, const float* __restrict__ w4,
                                     const float* __restrict__ w5, const void* edges) {
    int i = blockIdx.x * blockDim.x + threadIdx.x;
    // merged preprocessing (independent of weight conversion)
    if (i < NNODES) g_deg[i] = 0;
    if (i == 0) {
        const long long* p = (const long long*)edges;
        int is64 = 1;
        for (int k = 0; k < 16; k++) {
            long long v = p[k];
            if (v < 0 || v >= NNODES) is64 = 0;
        }
        g_is64 = is64;
    }
    if (i >= 692224) return;
    const float* src;
    int local;
    if (i < c_woff4[1])      { src = w1; local = i; }
    else if (i < c_woff4[2]) { src = w2; local = i - c_woff4[1]; }
    else if (i < c_woff4[3]) { src = w3; local = i - c_woff4[2]; }
    else if (i < c_woff4[4]) { src = w4; local = i - c_woff4[3]; }
    else                     { src = w5; local = i - c_woff4[4]; }
    float4 v = ((const float4*)src)[local];
    uint2 hi, lo;
    split4(v, hi, lo);
    ((uint2*)g_Whi)[i] = hi;
    ((uint2*)g_Wlo)[i] = lo;
}

// ==================== graph preprocessing ====================
__device__ __forceinline__ int edge_val(const void* edges, int idx) {
    if (g_is64) return (int)((const long long*)edges)[idx];
    return ((const int*)edges)[idx];
}
__global__ void count_deg_kernel(const void* edges) {
    int e = blockIdx.x * blockDim.x + threadIdx.x;
    if (e < NEDGES) atomicAdd(&g_deg[edge_val(edges, NEDGES + e)], 1);
}
__global__ void scan_kernel() {
    __shared__ int part[1024];
    int t = threadIdx.x;
    int c0 = g_deg[2 * t];
    int c1 = g_deg[2 * t + 1];
    part[t] = c0 + c1;
    __syncthreads();
    for (int off = 1; off < 1024; off <<= 1) {
        int v = (t >= off) ? part[t - off] : 0;
        __syncthreads();
        part[t] += v;
        __syncthreads();
    }
    int base = (t > 0) ? part[t - 1] : 0;
    g_off[2 * t] = base;        g_off[2 * t + 1] = base + c0;
    g_cursor[2 * t] = base;     g_cursor[2 * t + 1] = base + c0;
    g_dinv[2 * t]     = rsqrtf((float)(c0 + 1));
    g_dinv[2 * t + 1] = rsqrtf((float)(c1 + 1));
    if (t == 1023) g_off[2048] = part[1023];
}
__global__ void fill_kernel(const void* edges) {
    int e = blockIdx.x * blockDim.x + threadIdx.x;
    if (e < NEDGES) {
        int s = edge_val(edges, e);
        int d = edge_val(edges, NEDGES + e);
        int p = atomicAdd(&g_cursor[d], 1);
        g_csr_src[p]  = s;
        g_csr_norm[p] = g_dinv[s] * g_dinv[d];
    }
}

// ==================== aggregation fp32 input (layers 0-1), unroll-2 ====================
template <int F, bool BN>
__global__ void agg_kernel(const float* __restrict__ Hsrc,
                           __half* __restrict__ Phi, __half* __restrict__ Plo) {
    constexpr int F4 = F / 4;
    int b = blockIdx.y;
    if (blockIdx.x == 0) {
        int ft = threadIdx.y * blockDim.x + threadIdx.x;
        for (int i = ft; i < FMAX; i += 256) {
            g_sum[b * FMAX + i]  = 0.f;
            g_sum2[b * FMAX + i] = 0.f;
        }
    }
    int node = blockIdx.x * blockDim.y + threadIdx.y;
    int f4   = threadIdx.x;
    const float4* Hb = reinterpret_cast<const float4*>(Hsrc) + (size_t)b * NNODES * F4;

    float wself = g_dinv[node] * g_dinv[node];
    float4 hv = Hb[(size_t)node * F4 + f4];
    float4 acc = make_float4(wself * hv.x, wself * hv.y, wself * hv.z, wself * hv.w);
    float4 acc2 = make_float4(0.f, 0.f, 0.f, 0.f);
    float wsum = wself, wsum2 = 0.f;

    int beg = g_off[node], end = g_off[node + 1];
    int e = beg;
    for (; e + 2 <= end; e += 2) {
        int   s0 = g_csr_src[e],  s1 = g_csr_src[e + 1];
        float w0 = g_csr_norm[e], w1 = g_csr_norm[e + 1];
        float4 h0 = Hb[(size_t)s0 * F4 + f4];
        float4 h1 = Hb[(size_t)s1 * F4 + f4];
        acc.x  += w0 * h0.x; acc.y  += w0 * h0.y; acc.z  += w0 * h0.z; acc.w  += w0 * h0.w;
        acc2.x += w1 * h1.x; acc2.y += w1 * h1.y; acc2.z += w1 * h1.z; acc2.w += w1 * h1.w;
        wsum += w0; wsum2 += w1;
    }
    if (e < end) {
        int   s = g_csr_src[e];
        float w = g_csr_norm[e];
        float4 h = Hb[(size_t)s * F4 + f4];
        acc.x += w * h.x; acc.y += w * h.y; acc.z += w * h.z; acc.w += w * h.w;
        wsum += w;
    }
    acc.x += acc2.x; acc.y += acc2.y; acc.z += acc2.z; acc.w += acc2.w;
    wsum += wsum2;

    if (BN) {
        float4 al = ((const float4*)g_alpha)[b * (FMAX / 4) + f4];
        float4 bt = ((const float4*)g_beta)[b * (FMAX / 4) + f4];
        acc.x = acc.x * al.x + bt.x * wsum;
        acc.y = acc.y * al.y + bt.y * wsum;
        acc.z = acc.z * al.z + bt.z * wsum;
        acc.w = acc.w * al.w + bt.w * wsum;
    }
    uint2 hi, lo;
    split4(acc, hi, lo);
    size_t idx = ((size_t)b * NNODES + node) * F4 + f4;
    ((uint2*)Phi)[idx] = hi;
    ((uint2*)Plo)[idx] = lo;
}

// ==================== aggregation fp16 input (F=512/1024), 8 feats/thread, 16B loads, unroll-4 ====================
__device__ __forceinline__ void h8_to_f(const uint4 u, float* f) {
    float2 a = __half22float2(*(__half2*)&u.x);
    float2 b = __half22float2(*(__half2*)&u.y);
    float2 c = __half22float2(*(__half2*)&u.z);
    float2 d = __half22float2(*(__half2*)&u.w);
    f[0] = a.x; f[1] = a.y; f[2] = b.x; f[3] = b.y;
    f[4] = c.x; f[5] = c.y; f[6] = d.x; f[7] = d.y;
}
template <int F>
__global__ __launch_bounds__(256) void agg_f16_kernel(
    const __half* __restrict__ Hsrc, __half* __restrict__ Phi, __half* __restrict__ Plo) {
    constexpr int F8 = F / 8;
    int b = blockIdx.y;
    if (blockIdx.x == 0) {
        int ft = threadIdx.y * blockDim.x + threadIdx.x;
        for (int i = ft; i < FMAX; i += 256) {
            g_sum[b * FMAX + i]  = 0.f;
            g_sum2[b * FMAX + i] = 0.f;
        }
    }
    int node = blockIdx.x * blockDim.y + threadIdx.y;
    int f8   = threadIdx.x;
    const uint4* Hb = reinterpret_cast<const uint4*>(Hsrc) + (size_t)b * NNODES * F8;

    float wself = g_dinv[node] * g_dinv[node];
    float hv[8];
    h8_to_f(Hb[(size_t)node * F8 + f8], hv);
    float acc[8], acc2[8];
#pragma unroll
    for (int j = 0; j < 8; j++) { acc[j] = wself * hv[j]; acc2[j] = 0.f; }
    float wsum = wself, wsum2 = 0.f;

    int beg = g_off[node], end = g_off[node + 1];
    int e = beg;
    for (; e + 4 <= end; e += 4) {
        int   s0 = g_csr_src[e],     s1 = g_csr_src[e + 1];
        int   s2 = g_csr_src[e + 2], s3 = g_csr_src[e + 3];
        float w0 = g_csr_norm[e],     w1 = g_csr_norm[e + 1];
        float w2 = g_csr_norm[e + 2], w3 = g_csr_norm[e + 3];
        uint4 u0 = Hb[(size_t)s0 * F8 + f8];
        uint4 u1 = Hb[(size_t)s1 * F8 + f8];
        uint4 u2 = Hb[(size_t)s2 * F8 + f8];
        uint4 u3 = Hb[(size_t)s3 * F8 + f8];
        float h0[8], h1[8], h2[8], h3[8];
        h8_to_f(u0, h0); h8_to_f(u1, h1); h8_to_f(u2, h2); h8_to_f(u3, h3);
#pragma unroll
        for (int j = 0; j < 8; j++) {
            acc[j]  += w0 * h0[j] + w2 * h2[j];
            acc2[j] += w1 * h1[j] + w3 * h3[j];
        }
        wsum += w0 + w2; wsum2 += w1 + w3;
    }
    for (; e < end; e++) {
        int   s = g_csr_src[e];
        float w = g_csr_norm[e];
        float h[8];
        h8_to_f(Hb[(size_t)s * F8 + f8], h);
#pragma unroll
        for (int j = 0; j < 8; j++) acc[j] += w * h[j];
        wsum += w;
    }
#pragma unroll
    for (int j = 0; j < 8; j++) acc[j] += acc2[j];
    wsum += wsum2;

    // BN affine (8 channels)
    float4 al0 = ((const float4*)g_alpha)[b * (FMAX / 4) + f8 * 2];
    float4 al1 = ((const float4*)g_alpha)[b * (FMAX / 4) + f8 * 2 + 1];
    float4 bt0 = ((const float4*)g_beta)[b * (FMAX / 4) + f8 * 2];
    float4 bt1 = ((const float4*)g_beta)[b * (FMAX / 4) + f8 * 2 + 1];
    float4 r0 = make_float4(acc[0] * al0.x + bt0.x * wsum, acc[1] * al0.y + bt0.y * wsum,
                            acc[2] * al0.z + bt0.z * wsum, acc[3] * al0.w + bt0.w * wsum);
    float4 r1 = make_float4(acc[4] * al1.x + bt1.x * wsum, acc[5] * al1.y + bt1.y * wsum,
                            acc[6] * al1.z + bt1.z * wsum, acc[7] * al1.w + bt1.w * wsum);
    uint2 hiA, loA, hiB, loB;
    split4(r0, hiA, loA);
    split4(r1, hiB, loB);
    size_t idx = ((size_t)b * NNODES + node) * F8 + f8;
    ((uint4*)Phi)[idx] = make_uint4(hiA.x, hiA.y, hiB.x, hiB.y);
    ((uint4*)Plo)[idx] = make_uint4(loA.x, loA.y, loB.x, loB.y);
}

// ==================== mma.sync GEMM: 128 thr, warp tile 64x64, 2-stage, 2 CTA/SM ====================
#define TK        32
#define SM_STRIDE 80
#define MAT_BYTES (128 * SM_STRIDE)       // 10240
#define STAGE_BYTES (4 * MAT_BYTES)       // 40960
#define GEMM_SMEM (2 * STAGE_BYTES)       // 81920

__device__ __forceinline__ void cp_async16(uint32_t saddr, const void* gptr) {
    asm volatile("cp.async.cg.shared.global [%0], [%1], 16;" :: "r"(saddr), "l"(gptr));
}
__device__ __forceinline__ void ldm_x4(uint32_t* r, uint32_t addr) {
    asm volatile("ldmatrix.sync.aligned.m8n8.x4.shared.b16 {%0,%1,%2,%3}, [%4];"
        : "=r"(r[0]), "=r"(r[1]), "=r"(r[2]), "=r"(r[3]) : "r"(addr));
}
__device__ __forceinline__ void mma16816(float* c, const uint32_t* a, const uint32_t* b) {
    asm volatile("mma.sync.aligned.m16n8k16.row.col.f32.f16.f16.f32 "
        "{%0,%1,%2,%3}, {%4,%5,%6,%7}, {%8,%9}, {%0,%1,%2,%3};"
        : "+f"(c[0]), "+f"(c[1]), "+f"(c[2]), "+f"(c[3])
        : "r"(a[0]), "r"(a[1]), "r"(a[2]), "r"(a[3]), "r"(b[0]), "r"(b[1]));
}
__device__ __forceinline__ uint32_t smem_u32(const void* p) {
    uint32_t a;
    asm("{ .reg .u64 t; cvta.to.shared.u64 t, %1; cvt.u32.u64 %0, t; }" : "=r"(a) : "l"(p));
    return a;
}

template <bool HALF_OUT>
__global__ __launch_bounds__(128, 2) void mma_gemm_kernel(
    const __half* __restrict__ Ahi, const __half* __restrict__ Alo,
    const __half* __restrict__ Bhi, const __half* __restrict__ Blo,
    const float* __restrict__ bias, void* __restrict__ Cout, int K, int O) {
    extern __shared__ __align__(16) char smem[];
    uint32_t sb = smem_u32(smem);
    int tid  = threadIdx.x;
    int lane = tid & 31, wid = tid >> 5;
    int wm = wid >> 1, wn = wid & 1;
    int brow = blockIdx.y * 128;
    int bcol = blockIdx.x * 128;

    float acc[4][32];
#pragma unroll
    for (int i = 0; i < 4; i++)
#pragma unroll
        for (int j = 0; j < 32; j++) acc[i][j] = 0.f;

    const int NC = K / TK;
    auto load_stage = [&](int i) {
        int kc = i * TK;
        uint32_t st = sb + (uint32_t)(i & 1) * STAGE_BYTES;
#pragma unroll
        for (int c = 0; c < 4; c++) {
            int idx = tid + 128 * c;
            int row = idx >> 2, q = idx & 3;
            uint32_t soff = (uint32_t)(row * SM_STRIDE + q * 16);
            size_t gA = (size_t)(brow + row) * K + kc + q * 8;
            size_t gB = (size_t)(bcol + row) * K + kc + q * 8;
            cp_async16(st + soff,                 Ahi + gA);
            cp_async16(st + MAT_BYTES + soff,     Alo + gA);
            cp_async16(st + 2 * MAT_BYTES + soff, Bhi + gB);
            cp_async16(st + 3 * MAT_BYTES + soff, Blo + gB);
        }
        asm volatile("cp.async.commit_group;");
    };

    int grp = lane >> 3, l7 = lane & 7;
    uint32_t aOff = (uint32_t)((wm * 64 + (grp & 1) * 8 + l7) * SM_STRIDE + (grp >> 1) * 16);
    uint32_t bOff = (uint32_t)((wn * 64 + (grp >> 1) * 8 + l7) * SM_STRIDE + (grp & 1) * 16);

    load_stage(0);
    for (int i = 0; i < NC; i++) {
        if (i + 1 < NC) {
            load_stage(i + 1);
            asm volatile("cp.async.wait_group 1;");
        } else {
            asm volatile("cp.async.wait_group 0;");
        }
        __syncthreads();
        uint32_t st = sb + (uint32_t)(i & 1) * STAGE_BYTES;
#pragma unroll
        for (int ks = 0; ks < 2; ks++) {
            uint32_t ah[4][4], al[4][4], bh[4][4], bl[4][4];
#pragma unroll
            for (int mt = 0; mt < 4; mt++) {
                uint32_t a = st + aOff + (uint32_t)(mt * 16 * SM_STRIDE + ks * 32);
                ldm_x4(ah[mt], a);
                ldm_x4(al[mt], a + MAT_BYTES);
            }
#pragma unroll
            for (int ng = 0; ng < 4; ng++) {
                uint32_t b = st + 2 * MAT_BYTES + bOff + (uint32_t)(ng * 16 * SM_STRIDE + ks * 32);
                ldm_x4(bh[ng], b);
                ldm_x4(bl[ng], b + MAT_BYTES);
            }
#pragma unroll
            for (int mt = 0; mt < 4; mt++)
#pragma unroll
                for (int n8 = 0; n8 < 8; n8++) {
                    float* cc = &acc[mt][n8 * 4];
                    const uint32_t* bhf = &bh[n8 >> 1][(n8 & 1) * 2];
                    const uint32_t* blf = &bl[n8 >> 1][(n8 & 1) * 2];
                    mma16816(cc, ah[mt], bhf);
                    mma16816(cc, al[mt], bhf);
                    mma16816(cc, ah[mt], blf);
                }
        }
        __syncthreads();
    }

    // epilogue: bias + leaky, store (fp32 or fp16), fused BN partial stats
    int b = brow >> 11;
    int r0base = brow + wm * 64 + (lane >> 2);
    int cbase  = bcol + wn * 64 + (lane & 3) * 2;
    float s0[8], q0[8], s1[8], q1[8];
#pragma unroll
    for (int n8 = 0; n8 < 8; n8++) { s0[n8] = q0[n8] = s1[n8] = q1[n8] = 0.f; }
#pragma unroll
    for (int mt = 0; mt < 4; mt++) {
#pragma unroll
        for (int n8 = 0; n8 < 8; n8++) {
            int c  = cbase + n8 * 8;
            float2 bz = *(const float2*)(bias + c);
            float* a4 = &acc[mt][n8 * 4];
            float v0 = a4[0] + bz.x, v1 = a4[1] + bz.y;
            float v2 = a4[2] + bz.x, v3 = a4[3] + bz.y;
            v0 = (v0 > 0.f) ? v0 : 0.01f * v0;
            v1 = (v1 > 0.f) ? v1 : 0.01f * v1;
            v2 = (v2 > 0.f) ? v2 : 0.01f * v2;
            v3 = (v3 > 0.f) ? v3 : 0.01f * v3;
            int r0 = r0base + mt * 16;
            if (HALF_OUT) {
                __half* C16 = (__half*)Cout;
                *(__half2*)(C16 + (size_t)r0 * O + c)       = __floats2half2_rn(v0, v1);
                *(__half2*)(C16 + (size_t)(r0 + 8) * O + c) = __floats2half2_rn(v2, v3);
            } else {
                float* C = (float*)Cout;
                *(float2*)(C + (size_t)r0 * O + c)       = make_float2(v0, v1);
                *(float2*)(C + (size_t)(r0 + 8) * O + c) = make_float2(v2, v3);
            }
            s0[n8] += v0 + v2;  q0[n8] += v0 * v0 + v2 * v2;
            s1[n8] += v1 + v3;  q1[n8] += v1 * v1 + v3 * v3;
        }
    }
#pragma unroll
    for (int n8 = 0; n8 < 8; n8++) {
        float a = s0[n8], bq = q0[n8], cs = s1[n8], dq = q1[n8];
#pragma unroll
        for (int m = 4; m <= 16; m <<= 1) {
            a  += __shfl_xor_sync(0xffffffffu, a,  m);
            bq += __shfl_xor_sync(0xffffffffu, bq, m);
            cs += __shfl_xor_sync(0xffffffffu, cs, m);
            dq += __shfl_xor_sync(0xffffffffu, dq, m);
        }
        if (lane < 4) {
            int c = cbase + n8 * 8;
            atomicAdd(&g_sum[b * FMAX + c],      a);
            atomicAdd(&g_sum2[b * FMAX + c],     bq);
            atomicAdd(&g_sum[b * FMAX + c + 1],  cs);
            atomicAdd(&g_sum2[b * FMAX + c + 1], dq);
        }
    }
}

// ==================== BN stats finalize ====================
__global__ void stats_final_kernel(const float* __restrict__ g, const float* __restrict__ be, int O) {
    int b = blockIdx.y;
    int o = blockIdx.x * 256 + threadIdx.x;
    float mu  = g_sum[b * FMAX + o] * (1.0f / NNODES);
    float var = g_sum2[b * FMAX + o] * (1.0f / NNODES) - mu * mu;
    if (var < 0.f) var = 0.f;
    float a = g[o] * rsqrtf(var + BN_EPS);
    g_alpha[b * FMAX + o] = a;
    g_beta[b * FMAX + o]  = be[o] - mu * a;
}

// ==================== final: BN apply + LayerNorm ====================
__global__ void final_kernel(const float* __restrict__ T, const float* __restrict__ ln_g,
                             const float* __restrict__ ln_b, float* __restrict__ out) {
    const int O = 1024;
    int b = blockIdx.y, n = blockIdx.x, t = threadIdx.x;
    size_t rowbase = ((size_t)b * NNODES + n) * O;
    float4 tv = ((const float4*)(T + rowbase))[t];
    float4 av = ((const float4*)g_alpha)[b * (FMAX / 4) + t];
    float4 cv = ((const float4*)g_beta)[b * (FMAX / 4) + t];
    float4 v;
    v.x = tv.x * av.x + cv.x; v.y = tv.y * av.y + cv.y;
    v.z = tv.z * av.z + cv.z; v.w = tv.w * av.w + cv.w;

    float s  = v.x + v.y + v.z + v.w;
    float s2 = v.x * v.x + v.y * v.y + v.z * v.z + v.w * v.w;
#pragma unroll
    for (int off = 16; off > 0; off >>= 1) {
        s  += __shfl_xor_sync(0xffffffffu, s, off);
        s2 += __shfl_xor_sync(0xffffffffu, s2, off);
    }
    __shared__ float ss[8], ss2[8];
    __shared__ float mu_s, r_s;
    int warp = t >> 5, lane = t & 31;
    if (lane == 0) { ss[warp] = s; ss2[warp] = s2; }
    __syncthreads();
    if (t == 0) {
        float S = 0.f, S2 = 0.f;
        for (int i = 0; i < 8; i++) { S += ss[i]; S2 += ss2[i]; }
        float mu  = S * (1.0f / O);
        float var = S2 * (1.0f / O) - mu * mu;
        if (var < 0.f) var = 0.f;
        mu_s = mu;
        r_s  = rsqrtf(var + BN_EPS);
    }
    __syncthreads();
    float mu = mu_s, r = r_s;
    float4 g4 = ((const float4*)ln_g)[t];
    float4 b4 = ((const float4*)ln_b)[t];
    float4 o;
    o.x = (v.x - mu) * r * g4.x + b4.x;
    o.y = (v.y - mu) * r * g4.y + b4.y;
    o.z = (v.z - mu) * r * g4.z + b4.z;
    o.w = (v.w - mu) * r * g4.w + b4.w;
    ((float4*)(out + rowbase))[t] = o;
}

// ==================== host ====================
extern "C" void kernel_launch(void* const* d_in, const int* in_sizes, int n_in,
                              void* d_out, int out_size) {
    const float *x, *w[5], *bb[5], *gg[5], *be[5], *lng, *lnb;
    const void* edges;
    if (in_sizes[0] == 16384) {
        for (int i = 0; i < 5; i++) {
            w[i]  = (const float*)d_in[4 * i + 0];
            bb[i] = (const float*)d_in[4 * i + 1];
            gg[i] = (const float*)d_in[4 * i + 2];
            be[i] = (const float*)d_in[4 * i + 3];
        }
        lng = (const float*)d_in[20];
        lnb = (const float*)d_in[21];
        x   = (const float*)d_in[22];
        edges = d_in[23];
    } else {
        x     = (const float*)d_in[0];
        edges = d_in[1];
        for (int i = 0; i < 5; i++) {
            w[i]  = (const float*)d_in[2 + 4 * i + 0];
            bb[i] = (const float*)d_in[2 + 4 * i + 1];
            gg[i] = (const float*)d_in[2 + 4 * i + 2];
            be[i] = (const float*)d_in[2 + 4 * i + 3];
        }
        lng = (const float*)d_in[22];
        lnb = (const float*)d_in[23];
    }

    static int smem_set = 0;
    if (!smem_set) {
        cudaFuncSetAttribute(mma_gemm_kernel<false>, cudaFuncAttributeMaxDynamicSharedMemorySize, GEMM_SMEM);
        cudaFuncSetAttribute(mma_gemm_kernel<true>,  cudaFuncAttributeMaxDynamicSharedMemorySize, GEMM_SMEM);
        smem_set = 1;
    }

    __half *Phi, *Plo, *Whi, *Wlo, *T16;
    float* T;
    cudaGetSymbolAddress((void**)&Phi, g_Phi);
    cudaGetSymbolAddress((void**)&Plo, g_Plo);
    cudaGetSymbolAddress((void**)&Whi, g_Whi);
    cudaGetSymbolAddress((void**)&Wlo, g_Wlo);
    cudaGetSymbolAddress((void**)&T,   g_T);
    cudaGetSymbolAddress((void**)&T16, g_T16);

    convert_all_w_kernel<<<(692224 + 255) / 256, 256>>>(w[0], w[1], w[2], w[3], w[4], edges);
    count_deg_kernel<<<NEDGES / 256, 256>>>(edges);
    scan_kernel<<<1, 1024>>>();
    fill_kernel<<<NEDGES / 256, 256>>>(edges);

    const int dout[5] = {256, 512, 1024, 1024, 1024};
    const int din[5]  = {64, 256, 512, 1024, 1024};
    const int woff[5] = {0, 16384, 147456, 671744, 1720320};
    for (int l = 0; l < 5; l++) {
        int K = din[l], O = dout[l];
        // aggregation: L0 reads x fp32; L1 reads T fp32 (K=256); L2-4 read T16 fp16
        if (l == 0)
            agg_kernel<64, false><<<dim3(NNODES / 16, NB), dim3(16, 16)>>>(x, Phi, Plo);
        else if (l == 1)
            agg_kernel<256, true><<<dim3(NNODES / 4, NB), dim3(64, 4)>>>(T, Phi, Plo);
        else if (l == 2)
            agg_f16_kernel<512><<<dim3(NNODES / 4, NB), dim3(64, 4)>>>(T16, Phi, Plo);
        else
            agg_f16_kernel<1024><<<dim3(NNODES / 2, NB), dim3(128, 2)>>>(T16, Phi, Plo);
        // GEMM: layers 1,2,3 emit fp16 hidden state; layer 0 fp32 (feeds fp32 agg); layer 4 fp32 (feeds LN)
        if (l >= 1 && l <= 3)
            mma_gemm_kernel<true><<<dim3(O / 128, NROWS / 128), 128, GEMM_SMEM>>>(
                Phi, Plo, Whi + woff[l], Wlo + woff[l], bb[l], (void*)T16, K, O);
        else
            mma_gemm_kernel<false><<<dim3(O / 128, NROWS / 128), 128, GEMM_SMEM>>>(
                Phi, Plo, Whi + woff[l], Wlo + woff[l], bb[l], (void*)T, K, O);
        stats_final_kernel<<<dim3(O / 256, NB), 256>>>(gg[l], be[l], O);
        if (l == 4) final_kernel<<<dim3(NNODES, NB), 256>>>(T, lng, lnb, (float*)d_out);
    }
}